// round 3
// baseline (speedup 1.0000x reference)
#include <cuda_runtime.h>

#define NN        1024
#define DEPTHN    2
#define TOTAL_AB  4092
#define WPC       4                 // warps (rows) per CTA
#define ROWPAD    (NN + (NN >> 5))  // skewed row buffer size (1056)

__device__ __forceinline__ int skew(int i) { return i + (i >> 5); }

__device__ __forceinline__ float sigmoidf_(float z) {
    return 1.0f / (1.0f + expf(-z));
}

// ---------------- small (in-register) perm factor, M = 4..32 ----------------
template<int M>
__device__ __forceinline__ void perm_small(float2 (&v)[32], float p0, float p1, float p2) {
    const float q0 = 1.0f - p0, q1 = 1.0f - p1, q2 = 1.0f - p2;
#pragma unroll
    for (int jb = 0; jb < 32; jb += M) {
        float2 t[M];
#pragma unroll
        for (int k = 0; k < M; ++k) t[k] = v[jb + k];
        // even/odd separation mix: eo[k] = t[2k] (k < M/2) else t[2(k-M/2)+1]
#pragma unroll
        for (int k = 0; k < M; ++k) {
            float2 e = (k < M / 2) ? t[2 * k] : t[2 * (k - M / 2) + 1];
            v[jb + k].x = q0 * t[k].x + p0 * e.x;
            v[jb + k].y = q0 * t[k].y + p0 * e.y;
        }
        // half-reversal mixes, done pairwise in place (M/2 is even for M>=4)
#pragma unroll
        for (int k = 0; k < M / 4; ++k) {
            int a = jb + k, b = jb + M / 2 - 1 - k;
            float2 va = v[a], vb = v[b];
            v[a].x = q1 * va.x + p1 * vb.x;  v[a].y = q1 * va.y + p1 * vb.y;
            v[b].x = q1 * vb.x + p1 * va.x;  v[b].y = q1 * vb.y + p1 * va.y;
            int c = jb + M / 2 + k, e2 = jb + M - 1 - k;
            float2 vc = v[c], ve = v[e2];
            v[c].x  = q2 * vc.x + p2 * ve.x; v[c].y  = q2 * vc.y + p2 * ve.y;
            v[e2].x = q2 * ve.x + p2 * vc.x; v[e2].y = q2 * ve.y + p2 * vc.y;
        }
    }
}

// ---------------- small (in-register) diag factor, M = 2..32 ----------------
// ab points at this factor's packed ABCD (float2 complex): A[k]=ab[k],
// B[k]=ab[M/2+k], C[k]=ab[M+k], D[k]=ab[3M/2+k].  y1 = A x1 + B x2 ; y2 = C x1 + D x2.
template<int M>
__device__ __forceinline__ void diag_small(float2 (&v)[32], const float2* __restrict__ ab) {
#pragma unroll
    for (int k = 0; k < M / 2; ++k) {
        const float2 A = ab[k];
        const float2 B = ab[M / 2 + k];
        const float2 C = ab[M + k];
        const float2 D = ab[M + M / 2 + k];
#pragma unroll
        for (int jb = 0; jb < 32; jb += M) {
            float2 x1 = v[jb + k], x2 = v[jb + k + M / 2];
            float yr1 = A.x * x1.x - A.y * x1.y + B.x * x2.x - B.y * x2.y;
            float yi1 = A.x * x1.y + A.y * x1.x + B.x * x2.y + B.y * x2.x;
            float yr2 = C.x * x1.x - C.y * x1.y + D.x * x2.x - D.y * x2.y;
            float yi2 = C.x * x1.y + C.y * x1.x + D.x * x2.y + D.y * x2.x;
            v[jb + k]         = make_float2(yr1, yi1);
            v[jb + k + M / 2] = make_float2(yr2, yi2);
        }
    }
}

__global__ void __launch_bounds__(WPC * 32)
butterfly_kernel(const float* __restrict__ x,
                 const float* __restrict__ perm_logit,
                 const float* __restrict__ abcd_f,
                 const float* __restrict__ bias,
                 float* __restrict__ out)
{
    __shared__ float2 rowbuf[WPC][ROWPAD];

    const int warp = threadIdx.x >> 5;
    const int lane = threadIdx.x & 31;
    const int row  = blockIdx.x * WPC + warp;
    float2* rb = rowbuf[warp];

    const float2* abcd = reinterpret_cast<const float2*>(abcd_f);

    // ---- coalesced load of the row into smem (imag = 0), then pick up chunk ----
    const float* xr = x + (size_t)row * NN;
#pragma unroll
    for (int it = 0; it < 8; ++it) {
        int p = it * 128 + lane * 4;
        float4 t = *reinterpret_cast<const float4*>(xr + p);
        rb[skew(p + 0)] = make_float2(t.x, 0.0f);
        rb[skew(p + 1)] = make_float2(t.y, 0.0f);
        rb[skew(p + 2)] = make_float2(t.z, 0.0f);
        rb[skew(p + 3)] = make_float2(t.w, 0.0f);
    }
    __syncwarp();

    float2 v[32];
#pragma unroll
    for (int j = 0; j < 32; ++j) v[j] = rb[skew(lane * 32 + j)];
    __syncwarp();   // everyone done reading before first overwrite of rb

#pragma unroll 1
    for (int d = 0; d < DEPTHN; ++d) {
        const float p0 = sigmoidf_(perm_logit[d * 3 + 0]);
        const float p1 = sigmoidf_(perm_logit[d * 3 + 1]);
        const float p2 = sigmoidf_(perm_logit[d * 3 + 2]);
        const float q0 = 1.0f - p0;
        const float2* ab_base = abcd + d * TOTAL_AB;

        // ---------- perm factors m = 4, 8, 16, 32 (registers) ----------
        perm_small<4 >(v, p0, p1, p2);
        perm_small<8 >(v, p0, p1, p2);
        perm_small<16>(v, p0, p1, p2);
        perm_small<32>(v, p0, p1, p2);

        // ---------- perm factors m = 64..1024 (smem, 2 passes) ----------
#pragma unroll 1
        for (int m = 64; m <= NN; m <<= 1) {
            const int hs = m >> 1;
            // pass A: even/odd separation mix
#pragma unroll
            for (int j = 0; j < 32; ++j) rb[skew(lane * 32 + j)] = v[j];
            __syncwarp();
#pragma unroll
            for (int j = 0; j < 32; ++j) {
                int i = lane * 32 + j;
                int q = i & (m - 1);
                int base = i - q;
                int src = (q < hs) ? (base + 2 * q) : (base + 2 * (q - hs) + 1);
                float2 e = rb[skew(src)];
                v[j].x = q0 * v[j].x + p0 * e.x;
                v[j].y = q0 * v[j].y + p0 * e.y;
            }
            __syncwarp();
            // pass B: reversal mix on each half
#pragma unroll
            for (int j = 0; j < 32; ++j) rb[skew(lane * 32 + j)] = v[j];
            __syncwarp();
#pragma unroll
            for (int j = 0; j < 32; ++j) {
                int i = lane * 32 + j;
                int q = i & (m - 1);
                bool hi = q >= hs;
                int qh = hi ? (q - hs) : q;
                int rsrc = (i - q) + (hi ? hs : 0) + (hs - 1 - qh);
                float2 r = rb[skew(rsrc)];
                float pp = hi ? p2 : p1;
                float qq = 1.0f - pp;
                v[j].x = qq * v[j].x + pp * r.x;
                v[j].y = qq * v[j].y + pp * r.y;
            }
            __syncwarp();
        }

        // ---------- diag factors m = 2..32 (registers, uniform coeffs) ----------
        diag_small<2 >(v, ab_base + 4088);
        diag_small<4 >(v, ab_base + 4080);
        diag_small<8 >(v, ab_base + 4064);
        diag_small<16>(v, ab_base + 4032);
        diag_small<32>(v, ab_base + 3968);

        // ---------- diag factors m = 64..1024 (shfl.xor pairing) ----------
        {
            int off = 3840;  // offset of m=64 factor
#pragma unroll 1
            for (int m = 64; m <= NN; m <<= 1) {
                const float2* __restrict__ ab = ab_base + off;
                const int mask = m >> 6;
                const int hs = m >> 1;
                const bool hi = (lane & mask) != 0;
#pragma unroll
                for (int j = 0; j < 32; ++j) {
                    float2 u;
                    u.x = __shfl_xor_sync(0xffffffffu, v[j].x, mask);
                    u.y = __shfl_xor_sync(0xffffffffu, v[j].y, mask);
                    int i = lane * 32 + j;
                    int k = i & (hs - 1);
                    float2 P = ab[(hi ? m : 0) + k];          // A or C
                    float2 Q = ab[(hi ? (m + hs) : hs) + k];  // B or D
                    float2 xf = hi ? u : v[j];                // x1 (first half)
                    float2 xs = hi ? v[j] : u;                // x2 (second half)
                    float yr = P.x * xf.x - P.y * xf.y + Q.x * xs.x - Q.y * xs.y;
                    float yi = P.x * xf.y + P.y * xf.x + Q.x * xs.y + Q.y * xs.x;
                    v[j] = make_float2(yr, yi);
                }
                off -= 4 * m;  // offset of next (2m) factor: off(2m) = off(m) - 2*(2m)
            }
        }
    }

    // ---- write back: real part + bias, coalesced via smem ----
#pragma unroll
    for (int j = 0; j < 32; ++j) rb[skew(lane * 32 + j)] = v[j];
    __syncwarp();
    float* orow = out + (size_t)row * NN;
#pragma unroll
    for (int it = 0; it < 8; ++it) {
        int p = it * 128 + lane * 4;
        float4 bb = *reinterpret_cast<const float4*>(bias + p);
        float4 t;
        t.x = rb[skew(p + 0)].x + bb.x;
        t.y = rb[skew(p + 1)].x + bb.y;
        t.z = rb[skew(p + 2)].x + bb.z;
        t.w = rb[skew(p + 3)].x + bb.w;
        *reinterpret_cast<float4*>(orow + p) = t;
    }
}

extern "C" void kernel_launch(void* const* d_in, const int* in_sizes, int n_in,
                              void* d_out, int out_size)
{
    const float* x    = (const float*)d_in[0];
    const float* pl   = (const float*)d_in[1];
    const float* abcd = (const float*)d_in[2];
    const float* b    = (const float*)d_in[3];
    float* out = (float*)d_out;

    int rows = in_sizes[0] / NN;           // 16384
    int ctas = rows / WPC;                 // 4096
    butterfly_kernel<<<ctas, WPC * 32>>>(x, pl, abcd, b, out);
}

// round 6
// speedup vs baseline: 1.1912x; 1.1912x over previous
#include <cuda_runtime.h>

#define NN        1024
#define DEPTHN    2
#define TOTAL_AB  4092
#define WPC       4                 // warps (rows) per CTA
#define ROWPAD    (NN + (NN >> 5))  // skewed row buffer size (1056)

__device__ __forceinline__ int skew(int i) { return i + (i >> 5); }

__device__ __forceinline__ float sigmoidf_(float z) {
    return 1.0f / (1.0f + expf(-z));
}

// ================= small (in-register) perm factor, REAL, M = 4..32 ==========
// eo mix done in place with only M/2 temps: save odds, then ascending writes.
template<int M>
__device__ __forceinline__ void perm_small_r(float (&v)[32], float p0, float p1, float p2) {
    const float q0 = 1.0f - p0, q1 = 1.0f - p1, q2 = 1.0f - p2;
#pragma unroll
    for (int jb = 0; jb < 32; jb += M) {
        float todd[M / 2];
#pragma unroll
        for (int k = 0; k < M / 2; ++k) todd[k] = v[jb + 2 * k + 1];
#pragma unroll
        for (int k = 0; k < M / 2; ++k)              // y[k] = q0 x[k] + p0 x[2k]
            v[jb + k] = q0 * v[jb + k] + p0 * v[jb + 2 * k];
#pragma unroll
        for (int k = 0; k < M / 2; ++k)              // y[M/2+k] = q0 x[M/2+k] + p0 x[2k+1]
            v[jb + M / 2 + k] = q0 * v[jb + M / 2 + k] + p0 * todd[k];
#pragma unroll
        for (int k = 0; k < M / 4; ++k) {            // half-reversal mixes, pairwise
            int a = jb + k, b = jb + M / 2 - 1 - k;
            float va = v[a], vb = v[b];
            v[a] = q1 * va + p1 * vb;  v[b] = q1 * vb + p1 * va;
            int c = jb + M / 2 + k, e = jb + M - 1 - k;
            float vc = v[c], ve = v[e];
            v[c] = q2 * vc + p2 * ve;  v[e] = q2 * ve + p2 * vc;
        }
    }
}

// ================= small (in-register) perm factor, COMPLEX ==================
template<int M>
__device__ __forceinline__ void perm_small_c(float2 (&v)[32], float p0, float p1, float p2) {
    const float q0 = 1.0f - p0, q1 = 1.0f - p1, q2 = 1.0f - p2;
#pragma unroll
    for (int jb = 0; jb < 32; jb += M) {
        float2 todd[M / 2];
#pragma unroll
        for (int k = 0; k < M / 2; ++k) todd[k] = v[jb + 2 * k + 1];
#pragma unroll
        for (int k = 0; k < M / 2; ++k) {
            float2 a = v[jb + k], e = v[jb + 2 * k];
            v[jb + k] = make_float2(q0 * a.x + p0 * e.x, q0 * a.y + p0 * e.y);
        }
#pragma unroll
        for (int k = 0; k < M / 2; ++k) {
            float2 a = v[jb + M / 2 + k], e = todd[k];
            v[jb + M / 2 + k] = make_float2(q0 * a.x + p0 * e.x, q0 * a.y + p0 * e.y);
        }
#pragma unroll
        for (int k = 0; k < M / 4; ++k) {
            int a = jb + k, b = jb + M / 2 - 1 - k;
            float2 va = v[a], vb = v[b];
            v[a] = make_float2(q1 * va.x + p1 * vb.x, q1 * va.y + p1 * vb.y);
            v[b] = make_float2(q1 * vb.x + p1 * va.x, q1 * vb.y + p1 * va.y);
            int c = jb + M / 2 + k, e = jb + M - 1 - k;
            float2 vc = v[c], ve = v[e];
            v[c] = make_float2(q2 * vc.x + p2 * ve.x, q2 * vc.y + p2 * ve.y);
            v[e] = make_float2(q2 * ve.x + p2 * vc.x, q2 * ve.y + p2 * vc.y);
        }
    }
}

// ======= large perm factors m=64..1024: eo via smem gather, reversal via shfl =
// Reversal map in contiguous layout: source register = 31-j (compile time),
// source lane = f(lane, m) only.  Processed as (j, 31-j) pairs: hazard-free.
__device__ __forceinline__ void perm_large_r(float (&v)[32], float* __restrict__ rbf,
                                             int lane, float p0, float p1, float p2) {
    const float q0 = 1.0f - p0;
#pragma unroll 1
    for (int m = 64; m <= NN; m <<= 1) {
        const int hs = m >> 1;
        __syncwarp();
#pragma unroll
        for (int j = 0; j < 32; ++j) rbf[skew(lane * 32 + j)] = v[j];
        __syncwarp();
#pragma unroll
        for (int j = 0; j < 32; ++j) {
            int i = lane * 32 + j;
            int q = i & (m - 1);
            int src = i + q - ((q >= hs) ? (m - 1) : 0);   // base+2q  or  base+2(q-hs)+1
            v[j] = q0 * v[j] + p0 * rbf[skew(src)];
        }
        const int m32 = m >> 5, h32 = m >> 6;
        const int la  = lane & (m32 - 1);
        const int lah = la & (h32 - 1);
        const int lsrc = (lane - la) + (la - lah) + (h32 - 1 - lah);
        const bool hi = la >= h32;
        const float pp = hi ? p2 : p1, qq = 1.0f - pp;
#pragma unroll
        for (int j = 0; j < 16; ++j) {
            int j2 = 31 - j;
            float a = __shfl_sync(0xffffffffu, v[j2], lsrc);
            float b = __shfl_sync(0xffffffffu, v[j],  lsrc);
            v[j]  = qq * v[j]  + pp * a;
            v[j2] = qq * v[j2] + pp * b;
        }
    }
}

__device__ __forceinline__ void perm_large_c(float2 (&v)[32], float2* __restrict__ rb,
                                             int lane, float p0, float p1, float p2) {
    const float q0 = 1.0f - p0;
#pragma unroll 1
    for (int m = 64; m <= NN; m <<= 1) {
        const int hs = m >> 1;
        __syncwarp();
#pragma unroll
        for (int j = 0; j < 32; ++j) rb[skew(lane * 32 + j)] = v[j];
        __syncwarp();
#pragma unroll
        for (int j = 0; j < 32; ++j) {
            int i = lane * 32 + j;
            int q = i & (m - 1);
            int src = i + q - ((q >= hs) ? (m - 1) : 0);
            float2 e = rb[skew(src)];
            v[j] = make_float2(q0 * v[j].x + p0 * e.x, q0 * v[j].y + p0 * e.y);
        }
        const int m32 = m >> 5, h32 = m >> 6;
        const int la  = lane & (m32 - 1);
        const int lah = la & (h32 - 1);
        const int lsrc = (lane - la) + (la - lah) + (h32 - 1 - lah);
        const bool hi = la >= h32;
        const float pp = hi ? p2 : p1, qq = 1.0f - pp;
#pragma unroll
        for (int j = 0; j < 16; ++j) {
            int j2 = 31 - j;
            float ax = __shfl_sync(0xffffffffu, v[j2].x, lsrc);
            float ay = __shfl_sync(0xffffffffu, v[j2].y, lsrc);
            float bx = __shfl_sync(0xffffffffu, v[j].x,  lsrc);
            float by = __shfl_sync(0xffffffffu, v[j].y,  lsrc);
            v[j]  = make_float2(qq * v[j].x  + pp * ax, qq * v[j].y  + pp * ay);
            v[j2] = make_float2(qq * v[j2].x + pp * bx, qq * v[j2].y + pp * by);
        }
    }
}

// ================= small diag factor, COMPLEX, M = 2..32 ======================
template<int M>
__device__ __forceinline__ void diag_small(float2 (&v)[32], const float2* __restrict__ ab) {
#pragma unroll
    for (int k = 0; k < M / 2; ++k) {
        const float2 A = ab[k];
        const float2 B = ab[M / 2 + k];
        const float2 C = ab[M + k];
        const float2 D = ab[M + M / 2 + k];
#pragma unroll
        for (int jb = 0; jb < 32; jb += M) {
            float2 x1 = v[jb + k], x2 = v[jb + k + M / 2];
            float yr1 = A.x * x1.x - A.y * x1.y + B.x * x2.x - B.y * x2.y;
            float yi1 = A.x * x1.y + A.y * x1.x + B.x * x2.y + B.y * x2.x;
            float yr2 = C.x * x1.x - C.y * x1.y + D.x * x2.x - D.y * x2.y;
            float yi2 = C.x * x1.y + C.y * x1.x + D.x * x2.y + D.y * x2.x;
            v[jb + k]         = make_float2(yr1, yi1);
            v[jb + k + M / 2] = make_float2(yr2, yi2);
        }
    }
}

// ================= large diag factors m=64..1024 via shfl.xor =================
__device__ __forceinline__ void diag_large(float2 (&v)[32],
                                           const float2* __restrict__ ab_base, int lane) {
    int off = 3840;  // offset of the m=64 factor
#pragma unroll 1
    for (int m = 64; m <= NN; m <<= 1) {
        const float2* __restrict__ ab = ab_base + off;
        const int mask = m >> 6;
        const int hs = m >> 1;
        const bool hi = (lane & mask) != 0;
#pragma unroll
        for (int j = 0; j < 32; ++j) {
            float2 u;
            u.x = __shfl_xor_sync(0xffffffffu, v[j].x, mask);
            u.y = __shfl_xor_sync(0xffffffffu, v[j].y, mask);
            int i = lane * 32 + j;
            int k = i & (hs - 1);
            float2 P = ab[(hi ? m : 0) + k];          // A or C
            float2 Q = ab[(hi ? (m + hs) : hs) + k];  // B or D
            float2 xf = hi ? u : v[j];
            float2 xs = hi ? v[j] : u;
            float yr = P.x * xf.x - P.y * xf.y + Q.x * xs.x - Q.y * xs.y;
            float yi = P.x * xf.y + P.y * xf.x + Q.x * xs.y + Q.y * xs.x;
            v[j] = make_float2(yr, yi);
        }
        off -= 4 * m;
    }
}

__global__ void __launch_bounds__(WPC * 32, 3)
butterfly_kernel(const float* __restrict__ x,
                 const float* __restrict__ perm_logit,
                 const float* __restrict__ abcd_f,
                 const float* __restrict__ bias,
                 float* __restrict__ out)
{
    __shared__ float2 rowbuf[WPC][ROWPAD];

    const int warp = threadIdx.x >> 5;
    const int lane = threadIdx.x & 31;
    const int row  = blockIdx.x * WPC + warp;
    float2* rb  = rowbuf[warp];
    float*  rbf = reinterpret_cast<float*>(rb);

    const float2* abcd = reinterpret_cast<const float2*>(abcd_f);

    // ---- coalesced load of the row into smem (real only), then per-lane chunk ----
    const float* xr = x + (size_t)row * NN;
#pragma unroll
    for (int it = 0; it < 8; ++it) {
        int p = it * 128 + lane * 4;
        float4 t = *reinterpret_cast<const float4*>(xr + p);
        rbf[skew(p + 0)] = t.x;
        rbf[skew(p + 1)] = t.y;
        rbf[skew(p + 2)] = t.z;
        rbf[skew(p + 3)] = t.w;
    }
    __syncwarp();
    float vr[32];
#pragma unroll
    for (int j = 0; j < 32; ++j) vr[j] = rbf[skew(lane * 32 + j)];

    // ======================= depth 0: perms are purely REAL ===================
    {
        const float p0 = sigmoidf_(perm_logit[0]);
        const float p1 = sigmoidf_(perm_logit[1]);
        const float p2 = sigmoidf_(perm_logit[2]);
        perm_small_r<4 >(vr, p0, p1, p2);
        perm_small_r<8 >(vr, p0, p1, p2);
        perm_small_r<16>(vr, p0, p1, p2);
        perm_small_r<32>(vr, p0, p1, p2);
        perm_large_r(vr, rbf, lane, p0, p1, p2);
    }

    // ---- first diag (m=2) with imag==0 input: real->complex expansion ----
    float2 v[32];
    {
        const float2* ab = abcd + 4088;   // depth-0 base + m=2 offset
        const float2 A = ab[0], B = ab[1], C = ab[2], D = ab[3];
#pragma unroll
        for (int jb = 0; jb < 32; jb += 2) {
            float x1 = vr[jb], x2 = vr[jb + 1];
            v[jb]     = make_float2(A.x * x1 + B.x * x2, A.y * x1 + B.y * x2);
            v[jb + 1] = make_float2(C.x * x1 + D.x * x2, C.y * x1 + D.y * x2);
        }
    }
    diag_small<4 >(v, abcd + 4080);
    diag_small<8 >(v, abcd + 4064);
    diag_small<16>(v, abcd + 4032);
    diag_small<32>(v, abcd + 3968);
    diag_large(v, abcd, lane);

    // ======================= depth 1: full complex ============================
    {
        const float p0 = sigmoidf_(perm_logit[3]);
        const float p1 = sigmoidf_(perm_logit[4]);
        const float p2 = sigmoidf_(perm_logit[5]);
        perm_small_c<4 >(v, p0, p1, p2);
        perm_small_c<8 >(v, p0, p1, p2);
        perm_small_c<16>(v, p0, p1, p2);
        perm_small_c<32>(v, p0, p1, p2);
        perm_large_c(v, rb, lane, p0, p1, p2);

        const float2* ab1 = abcd + TOTAL_AB;
        diag_small<2 >(v, ab1 + 4088);
        diag_small<4 >(v, ab1 + 4080);
        diag_small<8 >(v, ab1 + 4064);
        diag_small<16>(v, ab1 + 4032);
        diag_small<32>(v, ab1 + 3968);
        diag_large(v, ab1, lane);
    }

    // ---- write back: real part + bias, coalesced via smem (floats only) ----
    __syncwarp();
#pragma unroll
    for (int j = 0; j < 32; ++j) rbf[skew(lane * 32 + j)] = v[j].x;
    __syncwarp();
    float* orow = out + (size_t)row * NN;
#pragma unroll
    for (int it = 0; it < 8; ++it) {
        int p = it * 128 + lane * 4;
        float4 bb = *reinterpret_cast<const float4*>(bias + p);
        float4 t;
        t.x = rbf[skew(p + 0)] + bb.x;
        t.y = rbf[skew(p + 1)] + bb.y;
        t.z = rbf[skew(p + 2)] + bb.z;
        t.w = rbf[skew(p + 3)] + bb.w;
        *reinterpret_cast<float4*>(orow + p) = t;
    }
}

extern "C" void kernel_launch(void* const* d_in, const int* in_sizes, int n_in,
                              void* d_out, int out_size)
{
    const float* x    = (const float*)d_in[0];
    const float* pl   = (const float*)d_in[1];
    const float* abcd = (const float*)d_in[2];
    const float* b    = (const float*)d_in[3];
    float* out = (float*)d_out;

    int rows = in_sizes[0] / NN;           // 16384
    int ctas = rows / WPC;                 // 4096
    butterfly_kernel<<<ctas, WPC * 32>>>(x, pl, abcd, b, out);
}

// round 7
// speedup vs baseline: 3.0812x; 2.5866x over previous
#include <cuda_runtime.h>

#define NN        1024
#define DEPTHN    2
#define TOTAL_AB  4092
#define WPC       4                 // warps (rows) per CTA
#define ROWPAD    (NN + (NN >> 5))  // skewed plane size (1056 floats)

__device__ __forceinline__ int skew(int i) { return i + (i >> 5); }

__device__ __forceinline__ float sigmoidf_(float z) {
    return 1.0f / (1.0f + expf(-z));
}

// ================= small (in-register) perm factor, REAL, M = 4..32 ==========
// Contiguous layout: thread holds elements 32*lane + j.
template<int M>
__device__ __forceinline__ void perm_small_r(float (&v)[32], float p0, float p1, float p2) {
    const float q0 = 1.0f - p0, q1 = 1.0f - p1, q2 = 1.0f - p2;
#pragma unroll
    for (int jb = 0; jb < 32; jb += M) {
        float todd[M / 2];
#pragma unroll
        for (int k = 0; k < M / 2; ++k) todd[k] = v[jb + 2 * k + 1];
#pragma unroll
        for (int k = 0; k < M / 2; ++k)
            v[jb + k] = q0 * v[jb + k] + p0 * v[jb + 2 * k];
#pragma unroll
        for (int k = 0; k < M / 2; ++k)
            v[jb + M / 2 + k] = q0 * v[jb + M / 2 + k] + p0 * todd[k];
#pragma unroll
        for (int k = 0; k < M / 4; ++k) {
            int a = jb + k, b = jb + M / 2 - 1 - k;
            float va = v[a], vb = v[b];
            v[a] = q1 * va + p1 * vb;  v[b] = q1 * vb + p1 * va;
            int c = jb + M / 2 + k, e = jb + M - 1 - k;
            float vc = v[c], ve = v[e];
            v[c] = q2 * vc + p2 * ve;  v[e] = q2 * ve + p2 * vc;
        }
    }
}

// ================= small (in-register) perm factor, COMPLEX ==================
template<int M>
__device__ __forceinline__ void perm_small_c(float2 (&v)[32], float p0, float p1, float p2) {
    const float q0 = 1.0f - p0, q1 = 1.0f - p1, q2 = 1.0f - p2;
#pragma unroll
    for (int jb = 0; jb < 32; jb += M) {
        float2 todd[M / 2];
#pragma unroll
        for (int k = 0; k < M / 2; ++k) todd[k] = v[jb + 2 * k + 1];
#pragma unroll
        for (int k = 0; k < M / 2; ++k) {
            float2 a = v[jb + k], e = v[jb + 2 * k];
            v[jb + k] = make_float2(q0 * a.x + p0 * e.x, q0 * a.y + p0 * e.y);
        }
#pragma unroll
        for (int k = 0; k < M / 2; ++k) {
            float2 a = v[jb + M / 2 + k], e = todd[k];
            v[jb + M / 2 + k] = make_float2(q0 * a.x + p0 * e.x, q0 * a.y + p0 * e.y);
        }
#pragma unroll
        for (int k = 0; k < M / 4; ++k) {
            int a = jb + k, b = jb + M / 2 - 1 - k;
            float2 va = v[a], vb = v[b];
            v[a] = make_float2(q1 * va.x + p1 * vb.x, q1 * va.y + p1 * vb.y);
            v[b] = make_float2(q1 * vb.x + p1 * va.x, q1 * vb.y + p1 * va.y);
            int c = jb + M / 2 + k, e = jb + M - 1 - k;
            float2 vc = v[c], ve = v[e];
            v[c] = make_float2(q2 * vc.x + p2 * ve.x, q2 * vc.y + p2 * ve.y);
            v[e] = make_float2(q2 * ve.x + p2 * vc.x, q2 * ve.y + p2 * vc.y);
        }
    }
}

// ============ large perm factor, REAL, strided layout (lane + 32*j) ==========
// eo mix via one smem round-trip; reversal via shfl from lane (31-lane) with a
// compile-time register permutation.  FIRST=true: input v is in CONTIGUOUS
// layout (32*lane+j); the smem pass performs the layout change for free.
template<int M, bool FIRST>
__device__ __forceinline__ void perm_large_r(float (&v)[32], float* __restrict__ sr,
                                             int lane, float p0, float p1, float p2) {
    constexpr int M32 = M / 32, H32 = M / 64;
    const float q0 = 1.0f - p0;
    __syncwarp();
    if (FIRST) {
#pragma unroll
        for (int j = 0; j < 32; ++j) sr[skew(32 * lane + j)] = v[j];
    } else {
#pragma unroll
        for (int j = 0; j < 32; ++j) sr[skew(lane + 32 * j)] = v[j];
    }
    __syncwarp();
#pragma unroll
    for (int j = 0; j < 32; ++j) {
        int jm = j & (M32 - 1);
        bool hieo = jm >= H32;            // compile-time after unroll
        int i = lane + 32 * j;
        int q = i & (M - 1);
        int src = i + q - (hieo ? (M - 1) : 0);   // base+2q  or  base+2(q-hs)+1
        float xi = FIRST ? sr[skew(i)] : v[j];
        v[j] = q0 * xi + p0 * sr[skew(src)];
    }
    // reversal: source lane is 31-lane; source register j2 compile-time.
    const int rl = 31 - lane;
#pragma unroll
    for (int j = 0; j < 32; ++j) {
        int jm = j & (M32 - 1);
        bool hi = jm >= H32;
        int j2 = j - 2 * jm + (hi ? 2 * H32 : 0) + H32 - 1;
        float pp = hi ? p2 : p1;
        float qq = 1.0f - pp;
        if (j2 == j) {
            float a = __shfl_sync(0xffffffffu, v[j], rl);
            v[j] = qq * v[j] + pp * a;
        } else if (j2 > j) {
            float a = __shfl_sync(0xffffffffu, v[j2], rl);
            float b = __shfl_sync(0xffffffffu, v[j],  rl);
            v[j]  = qq * v[j]  + pp * a;
            v[j2] = qq * v[j2] + pp * b;
        }
    }
}

// ============ large perm factor, COMPLEX, strided layout (SoA smem) ==========
template<int M, bool FIRST>
__device__ __forceinline__ void perm_large_c(float2 (&v)[32],
                                             float* __restrict__ sr, float* __restrict__ si,
                                             int lane, float p0, float p1, float p2) {
    constexpr int M32 = M / 32, H32 = M / 64;
    const float q0 = 1.0f - p0;
    __syncwarp();
    if (FIRST) {
#pragma unroll
        for (int j = 0; j < 32; ++j) { int a = skew(32 * lane + j); sr[a] = v[j].x; si[a] = v[j].y; }
    } else {
#pragma unroll
        for (int j = 0; j < 32; ++j) { int a = skew(lane + 32 * j); sr[a] = v[j].x; si[a] = v[j].y; }
    }
    __syncwarp();
#pragma unroll
    for (int j = 0; j < 32; ++j) {
        int jm = j & (M32 - 1);
        bool hieo = jm >= H32;
        int i = lane + 32 * j;
        int q = i & (M - 1);
        int src = i + q - (hieo ? (M - 1) : 0);
        int sa = skew(src);
        float xr = FIRST ? sr[skew(i)] : v[j].x;
        float xi = FIRST ? si[skew(i)] : v[j].y;
        v[j].x = q0 * xr + p0 * sr[sa];
        v[j].y = q0 * xi + p0 * si[sa];
    }
    const int rl = 31 - lane;
#pragma unroll
    for (int j = 0; j < 32; ++j) {
        int jm = j & (M32 - 1);
        bool hi = jm >= H32;
        int j2 = j - 2 * jm + (hi ? 2 * H32 : 0) + H32 - 1;
        float pp = hi ? p2 : p1;
        float qq = 1.0f - pp;
        if (j2 == j) {
            float ax = __shfl_sync(0xffffffffu, v[j].x, rl);
            float ay = __shfl_sync(0xffffffffu, v[j].y, rl);
            v[j].x = qq * v[j].x + pp * ax;
            v[j].y = qq * v[j].y + pp * ay;
        } else if (j2 > j) {
            float ax = __shfl_sync(0xffffffffu, v[j2].x, rl);
            float ay = __shfl_sync(0xffffffffu, v[j2].y, rl);
            float bx = __shfl_sync(0xffffffffu, v[j].x,  rl);
            float by = __shfl_sync(0xffffffffu, v[j].y,  rl);
            v[j].x  = qq * v[j].x  + pp * ax;
            v[j].y  = qq * v[j].y  + pp * ay;
            v[j2].x = qq * v[j2].x + pp * bx;
            v[j2].y = qq * v[j2].y + pp * by;
        }
    }
}

// ================= small diag factor, COMPLEX, contiguous ====================
template<int M>
__device__ __forceinline__ void diag_small(float2 (&v)[32], const float2* __restrict__ ab) {
#pragma unroll
    for (int k = 0; k < M / 2; ++k) {
        const float2 A = ab[k];
        const float2 B = ab[M / 2 + k];
        const float2 C = ab[M + k];
        const float2 D = ab[M + M / 2 + k];
#pragma unroll
        for (int jb = 0; jb < 32; jb += M) {
            float2 x1 = v[jb + k], x2 = v[jb + k + M / 2];
            float yr1 = A.x * x1.x - A.y * x1.y + B.x * x2.x - B.y * x2.y;
            float yi1 = A.x * x1.y + A.y * x1.x + B.x * x2.y + B.y * x2.x;
            float yr2 = C.x * x1.x - C.y * x1.y + D.x * x2.x - D.y * x2.y;
            float yi2 = C.x * x1.y + C.y * x1.x + D.x * x2.y + D.y * x2.x;
            v[jb + k]         = make_float2(yr1, yi1);
            v[jb + k + M / 2] = make_float2(yr2, yi2);
        }
    }
}

// ====== large diag factor, strided layout: register-local pairing, ===========
// ====== coefficients coalesced across lanes (k = lane + 32*jm).   ===========
template<int M>
__device__ __forceinline__ void diag_large_s(float2 (&v)[32],
                                             const float2* __restrict__ ab, int lane) {
    constexpr int M32 = M / 32, H32 = M / 64, HS = M / 2;
#pragma unroll
    for (int j = 0; j < 32; ++j) {
        int jm = j & (M32 - 1);
        if (jm < H32) {                 // low half of the m-block; partner j+H32
            int j2 = j + H32;
            int k = lane + 32 * jm;     // consecutive across lanes
            float2 A = ab[k];
            float2 B = ab[HS + k];
            float2 C = ab[M + k];
            float2 D = ab[M + HS + k];
            float2 x1 = v[j], x2 = v[j2];
            float yr1 = A.x * x1.x - A.y * x1.y + B.x * x2.x - B.y * x2.y;
            float yi1 = A.x * x1.y + A.y * x1.x + B.x * x2.y + B.y * x2.x;
            float yr2 = C.x * x1.x - C.y * x1.y + D.x * x2.x - D.y * x2.y;
            float yi2 = C.x * x1.y + C.y * x1.x + D.x * x2.y + D.y * x2.x;
            v[j]  = make_float2(yr1, yi1);
            v[j2] = make_float2(yr2, yi2);
        }
    }
}

// ============================ layout transposes ==============================
__device__ __forceinline__ void tr_s2c_r(float (&v)[32], float* __restrict__ sr, int lane) {
    __syncwarp();
#pragma unroll
    for (int j = 0; j < 32; ++j) sr[skew(lane + 32 * j)] = v[j];
    __syncwarp();
#pragma unroll
    for (int j = 0; j < 32; ++j) v[j] = sr[skew(32 * lane + j)];
}
__device__ __forceinline__ void tr_s2c_c(float2 (&v)[32], float* __restrict__ sr,
                                         float* __restrict__ si, int lane) {
    __syncwarp();
#pragma unroll
    for (int j = 0; j < 32; ++j) { int a = skew(lane + 32 * j); sr[a] = v[j].x; si[a] = v[j].y; }
    __syncwarp();
#pragma unroll
    for (int j = 0; j < 32; ++j) { int a = skew(32 * lane + j); v[j].x = sr[a]; v[j].y = si[a]; }
}
__device__ __forceinline__ void tr_c2s_c(float2 (&v)[32], float* __restrict__ sr,
                                         float* __restrict__ si, int lane) {
    __syncwarp();
#pragma unroll
    for (int j = 0; j < 32; ++j) { int a = skew(32 * lane + j); sr[a] = v[j].x; si[a] = v[j].y; }
    __syncwarp();
#pragma unroll
    for (int j = 0; j < 32; ++j) { int a = skew(lane + 32 * j); v[j].x = sr[a]; v[j].y = si[a]; }
}

__global__ void __launch_bounds__(WPC * 32, 3)
butterfly_kernel(const float* __restrict__ x,
                 const float* __restrict__ perm_logit,
                 const float* __restrict__ abcd_f,
                 const float* __restrict__ bias,
                 float* __restrict__ out)
{
    __shared__ float splane[WPC][2][ROWPAD];

    const int warp = threadIdx.x >> 5;
    const int lane = threadIdx.x & 31;
    const int row  = blockIdx.x * WPC + warp;
    float* sr = splane[warp][0];
    float* si = splane[warp][1];

    const float2* abcd = reinterpret_cast<const float2*>(abcd_f);

    // ---- coalesced load of the row (real) into smem, pick up contiguous chunk ----
    const float* xr = x + (size_t)row * NN;
#pragma unroll
    for (int it = 0; it < 8; ++it) {
        int p = it * 128 + lane * 4;
        float4 t = *reinterpret_cast<const float4*>(xr + p);
        sr[skew(p + 0)] = t.x;
        sr[skew(p + 1)] = t.y;
        sr[skew(p + 2)] = t.z;
        sr[skew(p + 3)] = t.w;
    }
    __syncwarp();
    float vr[32];
#pragma unroll
    for (int j = 0; j < 32; ++j) vr[j] = sr[skew(lane * 32 + j)];

    // ======================= depth 0: perms are purely REAL ===================
    {
        const float p0 = sigmoidf_(perm_logit[0]);
        const float p1 = sigmoidf_(perm_logit[1]);
        const float p2 = sigmoidf_(perm_logit[2]);
        perm_small_r<4 >(vr, p0, p1, p2);
        perm_small_r<8 >(vr, p0, p1, p2);
        perm_small_r<16>(vr, p0, p1, p2);
        perm_small_r<32>(vr, p0, p1, p2);
        perm_large_r<64,   true >(vr, sr, lane, p0, p1, p2);
        perm_large_r<128,  false>(vr, sr, lane, p0, p1, p2);
        perm_large_r<256,  false>(vr, sr, lane, p0, p1, p2);
        perm_large_r<512,  false>(vr, sr, lane, p0, p1, p2);
        perm_large_r<1024, false>(vr, sr, lane, p0, p1, p2);
        tr_s2c_r(vr, sr, lane);   // back to contiguous for small diags
    }

    // ---- first diag (m=2) with imag==0 input: real->complex (contiguous) ----
    float2 v[32];
    {
        const float2* ab = abcd + 4088;
        const float2 A = ab[0], B = ab[1], C = ab[2], D = ab[3];
#pragma unroll
        for (int jb = 0; jb < 32; jb += 2) {
            float x1 = vr[jb], x2 = vr[jb + 1];
            v[jb]     = make_float2(A.x * x1 + B.x * x2, A.y * x1 + B.y * x2);
            v[jb + 1] = make_float2(C.x * x1 + D.x * x2, C.y * x1 + D.y * x2);
        }
    }
    diag_small<4 >(v, abcd + 4080);
    diag_small<8 >(v, abcd + 4064);
    diag_small<16>(v, abcd + 4032);
    diag_small<32>(v, abcd + 3968);
    tr_c2s_c(v, sr, si, lane);            // strided for large diags
    diag_large_s<64  >(v, abcd + 3840, lane);
    diag_large_s<128 >(v, abcd + 3584, lane);
    diag_large_s<256 >(v, abcd + 3072, lane);
    diag_large_s<512 >(v, abcd + 2048, lane);
    diag_large_s<1024>(v, abcd + 0,    lane);

    // ======================= depth 1: full complex ============================
    {
        const float p0 = sigmoidf_(perm_logit[3]);
        const float p1 = sigmoidf_(perm_logit[4]);
        const float p2 = sigmoidf_(perm_logit[5]);
        tr_s2c_c(v, sr, si, lane);        // contiguous for small perms
        perm_small_c<4 >(v, p0, p1, p2);
        perm_small_c<8 >(v, p0, p1, p2);
        perm_small_c<16>(v, p0, p1, p2);
        perm_small_c<32>(v, p0, p1, p2);
        perm_large_c<64,   true >(v, sr, si, lane, p0, p1, p2);
        perm_large_c<128,  false>(v, sr, si, lane, p0, p1, p2);
        perm_large_c<256,  false>(v, sr, si, lane, p0, p1, p2);
        perm_large_c<512,  false>(v, sr, si, lane, p0, p1, p2);
        perm_large_c<1024, false>(v, sr, si, lane, p0, p1, p2);
        tr_s2c_c(v, sr, si, lane);        // contiguous for small diags

        const float2* ab1 = abcd + TOTAL_AB;
        diag_small<2 >(v, ab1 + 4088);
        diag_small<4 >(v, ab1 + 4080);
        diag_small<8 >(v, ab1 + 4064);
        diag_small<16>(v, ab1 + 4032);
        diag_small<32>(v, ab1 + 3968);
        tr_c2s_c(v, sr, si, lane);        // strided for large diags
        diag_large_s<64  >(v, ab1 + 3840, lane);
        diag_large_s<128 >(v, ab1 + 3584, lane);
        diag_large_s<256 >(v, ab1 + 3072, lane);
        diag_large_s<512 >(v, ab1 + 2048, lane);
        diag_large_s<1024>(v, ab1 + 0,    lane);
    }

    // ---- write back: strided layout is already coalesced across lanes ----
    float* orow = out + (size_t)row * NN;
#pragma unroll
    for (int j = 0; j < 32; ++j) {
        int p = lane + 32 * j;
        orow[p] = v[j].x + bias[p];
    }
}

extern "C" void kernel_launch(void* const* d_in, const int* in_sizes, int n_in,
                              void* d_out, int out_size)
{
    const float* x    = (const float*)d_in[0];
    const float* pl   = (const float*)d_in[1];
    const float* abcd = (const float*)d_in[2];
    const float* b    = (const float*)d_in[3];
    float* out = (float*)d_out;

    int rows = in_sizes[0] / NN;           // 16384
    int ctas = rows / WPC;                 // 4096
    butterfly_kernel<<<ctas, WPC * 32>>>(x, pl, abcd, b, out);
}

// round 8
// speedup vs baseline: 3.7315x; 1.2111x over previous
#include <cuda_runtime.h>

#define NN        1024
#define DEPTHN    2
#define TOTAL_AB  4092
#define WPC       4                 // warps (rows) per CTA
#define ROWPAD    (NN + (NN >> 5))  // skewed plane size (1056 elements)

typedef unsigned long long u64;

__device__ __forceinline__ int skew(int i) { return i + (i >> 5); }

__device__ __forceinline__ float sigmoidf_(float z) {
    return 1.0f / (1.0f + expf(-z));
}

// ===================== f32x2 packed helpers (PTX-only) =======================
__device__ __forceinline__ u64 pk2(float x, float y) {
    u64 r; asm("mov.b64 %0,{%1,%2};" : "=l"(r) : "f"(x), "f"(y)); return r;
}
__device__ __forceinline__ float2 upk2(u64 v) {
    float2 r; asm("mov.b64 {%0,%1},%2;" : "=f"(r.x), "=f"(r.y) : "l"(v)); return r;
}
__device__ __forceinline__ u64 dup2(float x) { return pk2(x, x); }
__device__ __forceinline__ u64 swp2(u64 v) {
    u64 r;
    asm("{.reg .f32 a,b; mov.b64 {a,b},%1; mov.b64 %0,{b,a};}" : "=l"(r) : "l"(v));
    return r;
}
__device__ __forceinline__ u64 fma2_(u64 a, u64 b, u64 c) {
    u64 d; asm("fma.rn.f32x2 %0,%1,%2,%3;" : "=l"(d) : "l"(a), "l"(b), "l"(c)); return d;
}
__device__ __forceinline__ u64 mul2_(u64 a, u64 b) {
    u64 d; asm("mul.rn.f32x2 %0,%1,%2;" : "=l"(d) : "l"(a), "l"(b)); return d;
}
// lerp: q*x + p*e (elementwise on packed pair)
__device__ __forceinline__ u64 lerp2(u64 q, u64 x, u64 p, u64 e) {
    return fma2_(q, x, mul2_(p, e));
}

// ================= small (in-register) perm factor, REAL, M = 4..32 ==========
template<int M>
__device__ __forceinline__ void perm_small_r(float (&v)[32], float p0, float p1, float p2) {
    const float q0 = 1.0f - p0, q1 = 1.0f - p1, q2 = 1.0f - p2;
#pragma unroll
    for (int jb = 0; jb < 32; jb += M) {
        float todd[M / 2];
#pragma unroll
        for (int k = 0; k < M / 2; ++k) todd[k] = v[jb + 2 * k + 1];
#pragma unroll
        for (int k = 0; k < M / 2; ++k)
            v[jb + k] = q0 * v[jb + k] + p0 * v[jb + 2 * k];
#pragma unroll
        for (int k = 0; k < M / 2; ++k)
            v[jb + M / 2 + k] = q0 * v[jb + M / 2 + k] + p0 * todd[k];
#pragma unroll
        for (int k = 0; k < M / 4; ++k) {
            int a = jb + k, b = jb + M / 2 - 1 - k;
            float va = v[a], vb = v[b];
            v[a] = q1 * va + p1 * vb;  v[b] = q1 * vb + p1 * va;
            int c = jb + M / 2 + k, e = jb + M - 1 - k;
            float vc = v[c], ve = v[e];
            v[c] = q2 * vc + p2 * ve;  v[e] = q2 * ve + p2 * vc;
        }
    }
}

// ============ small perm factor, COMPLEX packed (contiguous layout) ==========
template<int M>
__device__ __forceinline__ void perm_small_p(u64 (&v)[32], u64 q02, u64 p02,
                                             u64 q12, u64 p12, u64 q22, u64 p22) {
#pragma unroll
    for (int jb = 0; jb < 32; jb += M) {
        u64 todd[M / 2];
#pragma unroll
        for (int k = 0; k < M / 2; ++k) todd[k] = v[jb + 2 * k + 1];
#pragma unroll
        for (int k = 0; k < M / 2; ++k)
            v[jb + k] = lerp2(q02, v[jb + k], p02, v[jb + 2 * k]);
#pragma unroll
        for (int k = 0; k < M / 2; ++k)
            v[jb + M / 2 + k] = lerp2(q02, v[jb + M / 2 + k], p02, todd[k]);
#pragma unroll
        for (int k = 0; k < M / 4; ++k) {
            int a = jb + k, b = jb + M / 2 - 1 - k;
            u64 va = v[a], vb = v[b];
            v[a] = lerp2(q12, va, p12, vb);
            v[b] = lerp2(q12, vb, p12, va);
            int c = jb + M / 2 + k, e = jb + M - 1 - k;
            u64 vc = v[c], ve = v[e];
            v[c] = lerp2(q22, vc, p22, ve);
            v[e] = lerp2(q22, ve, p22, vc);
        }
    }
}

// ============ large perm factor, REAL, strided layout (lane + 32*j) ==========
template<int M, bool FIRST>
__device__ __forceinline__ void perm_large_r(float (&v)[32], float* __restrict__ sr,
                                             int lane, float p0, float p1, float p2) {
    constexpr int M32 = M / 32, H32 = M / 64;
    const float q0 = 1.0f - p0;
    __syncwarp();
    if (FIRST) {
#pragma unroll
        for (int j = 0; j < 32; ++j) sr[skew(32 * lane + j)] = v[j];
    } else {
#pragma unroll
        for (int j = 0; j < 32; ++j) sr[skew(lane + 32 * j)] = v[j];
    }
    __syncwarp();
#pragma unroll
    for (int j = 0; j < 32; ++j) {
        int jm = j & (M32 - 1);
        bool hieo = jm >= H32;
        int i = lane + 32 * j;
        int q = i & (M - 1);
        int src = i + q - (hieo ? (M - 1) : 0);
        float xi = FIRST ? sr[skew(i)] : v[j];
        v[j] = q0 * xi + p0 * sr[skew(src)];
    }
    const int rl = 31 - lane;
#pragma unroll
    for (int j = 0; j < 32; ++j) {
        int jm = j & (M32 - 1);
        bool hi = jm >= H32;
        int j2 = j - 2 * jm + (hi ? 2 * H32 : 0) + H32 - 1;
        float pp = hi ? p2 : p1;
        float qq = 1.0f - pp;
        if (j2 == j) {
            float a = __shfl_sync(0xffffffffu, v[j], rl);
            v[j] = qq * v[j] + pp * a;
        } else if (j2 > j) {
            float a = __shfl_sync(0xffffffffu, v[j2], rl);
            float b = __shfl_sync(0xffffffffu, v[j],  rl);
            v[j]  = qq * v[j]  + pp * a;
            v[j2] = qq * v[j2] + pp * b;
        }
    }
}

// ===== large perm factor, COMPLEX packed, strided layout, u64 smem plane =====
template<int M, bool FIRST>
__device__ __forceinline__ void perm_large_p(u64 (&v)[32], u64* __restrict__ sp, int lane,
                                             u64 q02, u64 p02, u64 q12, u64 p12,
                                             u64 q22, u64 p22) {
    constexpr int M32 = M / 32, H32 = M / 64;
    __syncwarp();
    if (FIRST) {
#pragma unroll
        for (int j = 0; j < 32; ++j) sp[skew(32 * lane + j)] = v[j];
    } else {
#pragma unroll
        for (int j = 0; j < 32; ++j) sp[skew(lane + 32 * j)] = v[j];
    }
    __syncwarp();
#pragma unroll
    for (int j = 0; j < 32; ++j) {
        int jm = j & (M32 - 1);
        bool hieo = jm >= H32;
        int i = lane + 32 * j;
        int q = i & (M - 1);
        int src = i + q - (hieo ? (M - 1) : 0);
        u64 x = FIRST ? sp[skew(i)] : v[j];
        v[j] = lerp2(q02, x, p02, sp[skew(src)]);
    }
    const int rl = 31 - lane;
#pragma unroll
    for (int j = 0; j < 32; ++j) {
        int jm = j & (M32 - 1);
        bool hi = jm >= H32;
        int j2 = j - 2 * jm + (hi ? 2 * H32 : 0) + H32 - 1;
        u64 pp2 = hi ? p22 : p12;
        u64 qq2 = hi ? q22 : q12;
        if (j2 == j) {
            u64 a = __shfl_sync(0xffffffffu, v[j], rl);
            v[j] = lerp2(qq2, v[j], pp2, a);
        } else if (j2 > j) {
            u64 a = __shfl_sync(0xffffffffu, v[j2], rl);
            u64 b = __shfl_sync(0xffffffffu, v[j],  rl);
            v[j]  = lerp2(qq2, v[j],  pp2, a);
            v[j2] = lerp2(qq2, v[j2], pp2, b);
        }
    }
}

// ====== small diag, COMPLEX packed, contiguous; coeffs from smem dup table ===
// dup[k][8] = {(Ax,Ax),(-Ay,Ay),(Bx,Bx),(-By,By),(Cx,Cx),(-Cy,Cy),(Dx,Dx),(-Dy,Dy)}
// y1 = Ax2*x1 + Aym2*swap(x1) + Bx2*x2 + Bym2*swap(x2);  y2 analogous with C,D.
template<int M>
__device__ __forceinline__ void diag_small_p(u64 (&v)[32], const u64 (*__restrict__ dup)[8]) {
#pragma unroll
    for (int k = 0; k < M / 2; ++k) {
        const u64 Ax = dup[k][0], Ay = dup[k][1], Bx = dup[k][2], By = dup[k][3];
        const u64 Cx = dup[k][4], Cy = dup[k][5], Dx = dup[k][6], Dy = dup[k][7];
#pragma unroll
        for (int jb = 0; jb < 32; jb += M) {
            u64 x1 = v[jb + k], x2 = v[jb + k + M / 2];
            u64 x1s = swp2(x1), x2s = swp2(x2);
            v[jb + k]         = fma2_(Ax, x1, fma2_(Ay, x1s, fma2_(Bx, x2, mul2_(By, x2s))));
            v[jb + k + M / 2] = fma2_(Cx, x1, fma2_(Cy, x1s, fma2_(Dx, x2, mul2_(Dy, x2s))));
        }
    }
}

// ====== large diag, strided layout, u64 state, scalar math (coeffs coalesced) =
template<int M>
__device__ __forceinline__ void diag_large_su(u64 (&v)[32],
                                              const float2* __restrict__ ab, int lane) {
    constexpr int M32 = M / 32, H32 = M / 64, HS = M / 2;
#pragma unroll
    for (int j = 0; j < 32; ++j) {
        int jm = j & (M32 - 1);
        if (jm < H32) {
            int j2 = j + H32;
            int k = lane + 32 * jm;            // consecutive across lanes
            float2 A = ab[k];
            float2 B = ab[HS + k];
            float2 C = ab[M + k];
            float2 D = ab[M + HS + k];
            float2 x1 = upk2(v[j]), x2 = upk2(v[j2]);
            float yr1 = A.x * x1.x - A.y * x1.y + B.x * x2.x - B.y * x2.y;
            float yi1 = A.x * x1.y + A.y * x1.x + B.x * x2.y + B.y * x2.x;
            float yr2 = C.x * x1.x - C.y * x1.y + D.x * x2.x - D.y * x2.y;
            float yi2 = C.x * x1.y + C.y * x1.x + D.x * x2.y + D.y * x2.x;
            v[j]  = pk2(yr1, yi1);
            v[j2] = pk2(yr2, yi2);
        }
    }
}

// ============================ layout transposes ==============================
__device__ __forceinline__ void tr_s2c_r(float (&v)[32], float* __restrict__ sr, int lane) {
    __syncwarp();
#pragma unroll
    for (int j = 0; j < 32; ++j) sr[skew(lane + 32 * j)] = v[j];
    __syncwarp();
#pragma unroll
    for (int j = 0; j < 32; ++j) v[j] = sr[skew(32 * lane + j)];
}
__device__ __forceinline__ void tr_s2c_p(u64 (&v)[32], u64* __restrict__ sp, int lane) {
    __syncwarp();
#pragma unroll
    for (int j = 0; j < 32; ++j) sp[skew(lane + 32 * j)] = v[j];
    __syncwarp();
#pragma unroll
    for (int j = 0; j < 32; ++j) v[j] = sp[skew(32 * lane + j)];
}
__device__ __forceinline__ void tr_c2s_p(u64 (&v)[32], u64* __restrict__ sp, int lane) {
    __syncwarp();
#pragma unroll
    for (int j = 0; j < 32; ++j) sp[skew(32 * lane + j)] = v[j];
    __syncwarp();
#pragma unroll
    for (int j = 0; j < 32; ++j) v[j] = sp[skew(lane + 32 * j)];
}

__global__ void __launch_bounds__(WPC * 32, 3)
butterfly_kernel(const float* __restrict__ x,
                 const float* __restrict__ perm_logit,
                 const float* __restrict__ abcd_f,
                 const float* __restrict__ bias,
                 float* __restrict__ out)
{
    __shared__ u64 splane[WPC][ROWPAD];     // 33.8 KB: per-warp row plane
    __shared__ u64 sdup[2][31][8];          // 3.9 KB: packed small-diag coeffs

    const int warp = threadIdx.x >> 5;
    const int lane = threadIdx.x & 31;
    const int row  = blockIdx.x * WPC + warp;
    u64*   sp  = splane[warp];
    float* srf = reinterpret_cast<float*>(sp);   // float view for real sections

    const float2* abcd = reinterpret_cast<const float2*>(abcd_f);

    // ---- build packed coefficient table for small diags (both depths) ----
    for (int t = threadIdx.x; t < 62; t += blockDim.x) {
        int d = t / 31, s = t % 31;
        int M, k, fac;
        if      (s < 1)  { M = 2;  k = s;      fac = 4088; }
        else if (s < 3)  { M = 4;  k = s - 1;  fac = 4080; }
        else if (s < 7)  { M = 8;  k = s - 3;  fac = 4064; }
        else if (s < 15) { M = 16; k = s - 7;  fac = 4032; }
        else             { M = 32; k = s - 15; fac = 3968; }
        const float2* ab = abcd + d * TOTAL_AB + fac;
        float2 A = ab[k], B = ab[M / 2 + k], C = ab[M + k], D = ab[M + M / 2 + k];
        u64* o = sdup[d][s];
        o[0] = dup2(A.x); o[1] = pk2(-A.y, A.y);
        o[2] = dup2(B.x); o[3] = pk2(-B.y, B.y);
        o[4] = dup2(C.x); o[5] = pk2(-C.y, C.y);
        o[6] = dup2(D.x); o[7] = pk2(-D.y, D.y);
    }
    __syncthreads();

    // ---- coalesced load of the row (real) into smem, pick up contiguous chunk ----
    const float* xr = x + (size_t)row * NN;
#pragma unroll
    for (int it = 0; it < 8; ++it) {
        int p = it * 128 + lane * 4;
        float4 t = *reinterpret_cast<const float4*>(xr + p);
        srf[skew(p + 0)] = t.x;
        srf[skew(p + 1)] = t.y;
        srf[skew(p + 2)] = t.z;
        srf[skew(p + 3)] = t.w;
    }
    __syncwarp();
    float vr[32];
#pragma unroll
    for (int j = 0; j < 32; ++j) vr[j] = srf[skew(lane * 32 + j)];

    // ======================= depth 0: perms are purely REAL ===================
    {
        const float p0 = sigmoidf_(perm_logit[0]);
        const float p1 = sigmoidf_(perm_logit[1]);
        const float p2 = sigmoidf_(perm_logit[2]);
        perm_small_r<4 >(vr, p0, p1, p2);
        perm_small_r<8 >(vr, p0, p1, p2);
        perm_small_r<16>(vr, p0, p1, p2);
        perm_small_r<32>(vr, p0, p1, p2);
        perm_large_r<64,   true >(vr, srf, lane, p0, p1, p2);
        perm_large_r<128,  false>(vr, srf, lane, p0, p1, p2);
        perm_large_r<256,  false>(vr, srf, lane, p0, p1, p2);
        perm_large_r<512,  false>(vr, srf, lane, p0, p1, p2);
        perm_large_r<1024, false>(vr, srf, lane, p0, p1, p2);
        tr_s2c_r(vr, srf, lane);   // back to contiguous for diags
    }

    // ---- first diag (m=2) with imag==0 input: real -> packed complex ----
    u64 vc[32];
    {
        const u64* abq = reinterpret_cast<const u64*>(abcd + 4088);  // (Ax,Ay)(Bx,By)(Cx,Cy)(Dx,Dy)
        const u64 A = abq[0], B = abq[1], C = abq[2], D = abq[3];
#pragma unroll
        for (int jb = 0; jb < 32; jb += 2) {
            u64 x1 = dup2(vr[jb]), x2 = dup2(vr[jb + 1]);
            vc[jb]     = fma2_(A, x1, mul2_(B, x2));
            vc[jb + 1] = fma2_(C, x1, mul2_(D, x2));
        }
    }
    diag_small_p<4 >(vc, sdup[0] + 1);
    diag_small_p<8 >(vc, sdup[0] + 3);
    diag_small_p<16>(vc, sdup[0] + 7);
    diag_small_p<32>(vc, sdup[0] + 15);
    tr_c2s_p(vc, sp, lane);               // strided for large diags
    diag_large_su<64  >(vc, abcd + 3840, lane);
    diag_large_su<128 >(vc, abcd + 3584, lane);
    diag_large_su<256 >(vc, abcd + 3072, lane);
    diag_large_su<512 >(vc, abcd + 2048, lane);
    diag_large_su<1024>(vc, abcd + 0,    lane);

    // ======================= depth 1: full complex (packed) ===================
    {
        const float p0 = sigmoidf_(perm_logit[3]);
        const float p1 = sigmoidf_(perm_logit[4]);
        const float p2 = sigmoidf_(perm_logit[5]);
        const u64 p02 = dup2(p0), q02 = dup2(1.0f - p0);
        const u64 p12 = dup2(p1), q12 = dup2(1.0f - p1);
        const u64 p22 = dup2(p2), q22 = dup2(1.0f - p2);

        tr_s2c_p(vc, sp, lane);           // contiguous for small perms
        perm_small_p<4 >(vc, q02, p02, q12, p12, q22, p22);
        perm_small_p<8 >(vc, q02, p02, q12, p12, q22, p22);
        perm_small_p<16>(vc, q02, p02, q12, p12, q22, p22);
        perm_small_p<32>(vc, q02, p02, q12, p12, q22, p22);
        perm_large_p<64,   true >(vc, sp, lane, q02, p02, q12, p12, q22, p22);
        perm_large_p<128,  false>(vc, sp, lane, q02, p02, q12, p12, q22, p22);
        perm_large_p<256,  false>(vc, sp, lane, q02, p02, q12, p12, q22, p22);
        perm_large_p<512,  false>(vc, sp, lane, q02, p02, q12, p12, q22, p22);
        perm_large_p<1024, false>(vc, sp, lane, q02, p02, q12, p12, q22, p22);
        tr_s2c_p(vc, sp, lane);           // contiguous for small diags

        const float2* ab1 = abcd + TOTAL_AB;
        diag_small_p<2 >(vc, sdup[1] + 0);
        diag_small_p<4 >(vc, sdup[1] + 1);
        diag_small_p<8 >(vc, sdup[1] + 3);
        diag_small_p<16>(vc, sdup[1] + 7);
        diag_small_p<32>(vc, sdup[1] + 15);
        tr_c2s_p(vc, sp, lane);           // strided for large diags
        diag_large_su<64  >(vc, ab1 + 3840, lane);
        diag_large_su<128 >(vc, ab1 + 3584, lane);
        diag_large_su<256 >(vc, ab1 + 3072, lane);
        diag_large_su<512 >(vc, ab1 + 2048, lane);
        diag_large_su<1024>(vc, ab1 + 0,    lane);
    }

    // ---- write back: strided layout is already coalesced across lanes ----
    float* orow = out + (size_t)row * NN;
#pragma unroll
    for (int j = 0; j < 32; ++j) {
        int p = lane + 32 * j;
        float2 r = upk2(vc[j]);
        orow[p] = r.x + bias[p];
    }
}

extern "C" void kernel_launch(void* const* d_in, const int* in_sizes, int n_in,
                              void* d_out, int out_size)
{
    const float* x    = (const float*)d_in[0];
    const float* pl   = (const float*)d_in[1];
    const float* abcd = (const float*)d_in[2];
    const float* b    = (const float*)d_in[3];
    float* out = (float*)d_out;

    int rows = in_sizes[0] / NN;           // 16384
    int ctas = rows / WPC;                 // 4096
    butterfly_kernel<<<ctas, WPC * 32>>>(x, pl, abcd, b, out);
}